// round 10
// baseline (speedup 1.0000x reference)
#include <cuda_runtime.h>
#include <cuda_bf16.h>
#include <math.h>

#define N_PROP   65536
#define N_GT     64
#define NCLS     81
#define TOTAL    512
#define MAX_POS  128

#define K1_TPB   512
#define K1_NBLK  1024           // 8 threads/prop: 65536*8/512
#define K2_TPB   256
#define NGRP     256            // groups of 256 proposals
#define K3_TPB   128
#define K3_NBLK  128            // 4 warps each -> 512 slots

// -------- device scratch --------
__device__ int   g_res[N_PROP];       // f | (gt << 2)
__device__ int   g_grp_pos[NGRP];
__device__ int   g_grp_neg[NGRP];
__device__ int   g_npos, g_ntot;
__device__ int   g_pos_list[TOTAL];   // packed (gt<<16)|i
__device__ int   g_neg_list[TOTAL];
__device__ int   g_non_list[TOTAL];
__device__ float g_ce[TOTAL];
__device__ float g_rg[TOTAL];
__device__ int   g_done;

__device__ __forceinline__ float sl1(float d) {
    float ad = fabsf(d);
    return (ad < 1.0f) ? (0.5f * d * d) : (ad - 0.5f);
}

// ================= K1: IoU + classify (register-resident gts) =================
__global__ void __launch_bounds__(K1_TPB)
k_iou(const float* __restrict__ props, const float* __restrict__ gts) {
    __shared__ int wcp[K1_TPB / 32], wcn[K1_TPB / 32];

    const int t = threadIdx.x, bid = blockIdx.x;
    const int warp = t >> 5, lane = t & 31, oct = t & 7;
    const unsigned full = 0xffffffffu;

    const int i = (bid * K1_TPB + t) >> 3;       // proposal (8 lanes share)
    const float4 p = ((const float4*)props)[i];  // broadcast within octet
    const float pa = (p.z - p.x) * (p.w - p.y);

    // preload this octet-lane's 8 gts into registers (batched LDG, no LDS)
    const int jb = oct * 8;
    float4 G[8];
    float  GA[8], S[8];
#pragma unroll
    for (int k = 0; k < 8; k++) G[k] = ((const float4*)gts)[jb + k];
#pragma unroll
    for (int k = 0; k < 8; k++) {
        GA[k] = (G[k].z - G[k].x) * (G[k].w - G[k].y);
        S[k]  = GA[k] + 1e-8f;
    }

    // two independent chains over even/odd k (pure register math)
    float bi[2], bS[2], bga[2];
    int   bj[2];
#pragma unroll
    for (int c = 0; c < 2; c++) {
        int k = c;
        float ix = fmaxf(fminf(p.z, G[k].z) - fmaxf(p.x, G[k].x), 0.f);
        float iy = fmaxf(fminf(p.w, G[k].w) - fmaxf(p.y, G[k].y), 0.f);
        bi[c] = ix * iy; bS[c] = pa + S[k]; bga[c] = GA[k]; bj[c] = jb + k;
    }
#pragma unroll
    for (int k = 2; k < 8; k++) {
        const int c = k & 1;
        float ix = fmaxf(fminf(p.z, G[k].z) - fmaxf(p.x, G[k].x), 0.f);
        float iy = fmaxf(fminf(p.w, G[k].w) - fmaxf(p.y, G[k].y), 0.f);
        float in = ix * iy;
        float Sx = pa + S[k];
        // iou_new > iou_best <=> in*bS > bi*Sx (union -inter terms cancel exactly);
        // in-chain index always increases -> strict > keeps first argmax
        if (in * bS[c] > bi[c] * Sx) { bi[c] = in; bS[c] = Sx; bga[c] = GA[k]; bj[c] = jb + k; }
    }
    // merge chains + octet reduce with full tie rule: greater OR (equal AND lower index)
    float Bi = bi[0], BS = bS[0], Bga = bga[0];
    int   Bj = bj[0];
    {
        float l = bi[1] * BS, r = Bi * bS[1];
        if (l > r || (l == r && bj[1] < Bj)) { Bi = bi[1]; BS = bS[1]; Bga = bga[1]; Bj = bj[1]; }
    }
#pragma unroll
    for (int o = 4; o; o >>= 1) {
        float oi = __shfl_down_sync(full, Bi, o);
        float oS = __shfl_down_sync(full, BS, o);
        float og = __shfl_down_sync(full, Bga, o);
        int   oj = __shfl_down_sync(full, Bj, o);
        float l = oi * BS, r = Bi * oS;
        if (l > r || (l == r && oj < Bj)) { Bi = oi; BS = oS; Bga = og; Bj = oj; }
    }

    int f = 0;
    if (oct == 0) {
        // exact final iou in reference association order
        float u = ((pa + Bga) - Bi) + 1e-8f;
        float miou = Bi / u;
        f = (miou >= 0.5f) ? 1 : ((miou >= 0.1f) ? 2 : 0);
        g_res[i] = f | (Bj << 2);
    }
    unsigned bp = __ballot_sync(full, f == 1);
    unsigned bn = __ballot_sync(full, f == 2);
    if (lane == 0) { wcp[warp] = __popc(bp); wcn[warp] = __popc(bn); }
    __syncthreads();
    if (t == 0) {
        int cp = 0, cn = 0;
#pragma unroll
        for (int w = 0; w < K1_TPB / 32; w++) { cp += wcp[w]; cn += wcn[w]; }
        // block covers 64 props; group = 256 props -> gid = bid>>2
        if (cp) atomicAdd(&g_grp_pos[bid >> 2], cp);
        if (cn) atomicAdd(&g_grp_neg[bid >> 2], cn);
    }
}

// ================= K2: scan + stable select =================
__global__ void __launch_bounds__(K2_TPB)
k_sel() {
    __shared__ int wpc[8], wnc[8];
    __shared__ int swp[8], swn[8];
    __shared__ int ssp[NGRP], ssn[NGRP];
    __shared__ int s_offp, s_offn, s_numpos, s_negtot;

    const int t = threadIdx.x, bid = blockIdx.x;
    const int warp = t >> 5, lane = t & 31;
    const unsigned full = 0xffffffffu;

    const int i = bid * K2_TPB + t;
    const int res = __ldcg(&g_res[i]);
    const int f  = res & 3;
    const int bj = res >> 2;

    unsigned bp = __ballot_sync(full, f == 1);
    unsigned bn = __ballot_sync(full, f == 2);
    if (lane == 0) { wpc[warp] = __popc(bp); wnc[warp] = __popc(bn); }

    // scan 256 group counts (ready at kernel entry)
    {
        int ip  = __ldcg(&g_grp_pos[t]);
        int in_ = __ldcg(&g_grp_neg[t]);
#pragma unroll
        for (int o = 1; o < 32; o <<= 1) {
            int ap = __shfl_up_sync(full, ip, o);
            int an = __shfl_up_sync(full, in_, o);
            if (lane >= o) { ip += ap; in_ += an; }
        }
        if (lane == 31) { swp[warp] = ip; swn[warp] = in_; }
        __syncthreads();
        int basep = 0, basen = 0;
        for (int w = 0; w < warp; w++) { basep += swp[w]; basen += swn[w]; }
        ssp[t] = basep + ip;
        ssn[t] = basen + in_;
    }
    __syncthreads();
    if (t == 0) {
        s_offp   = (bid > 0) ? ssp[bid - 1] : 0;
        s_offn   = (bid > 0) ? ssn[bid - 1] : 0;
        s_numpos = min(ssp[NGRP - 1], MAX_POS);
        s_negtot = ssn[NGRP - 1];
        if (bid == 0) { g_npos = s_numpos; g_ntot = s_negtot; }
    }
    __syncthreads();

    {
        int pre_p = 0, pre_n = 0;
        for (int w = 0; w < warp; w++) { pre_p += wpc[w]; pre_n += wnc[w]; }
        unsigned lm = (1u << lane) - 1u;
        int neg_before = pre_n + __popc(bn & lm);
        if (f == 1) {
            int r = s_offp + pre_p + __popc(bp & lm);
            if (r < TOTAL) g_pos_list[r] = i | (bj << 16);
        } else if (f == 2) {
            int r = s_offn + neg_before;
            if (r < TOTAL) g_neg_list[r] = i;
        }
        if (f != 2) {
            int r = (bid * K2_TPB - s_offn) + (t - neg_before);
            if (r < TOTAL) g_non_list[r] = i;
        }
    }
}

// ================= K3: loss + last-arriver reduce =================
__global__ void __launch_bounds__(K3_TPB)
k_loss(const float* __restrict__ props,
       const float* __restrict__ gts,
       const int*   __restrict__ gt_labels,
       const float* __restrict__ score,
       const float* __restrict__ txty,
       float* __restrict__ out) {
    __shared__ float4 sg[N_GT];
    __shared__ int    slbl[N_GT];
    __shared__ int    s_last;
    __shared__ float  rc[4], rr[4];

    const int t = threadIdx.x, bid = blockIdx.x;
    const int warp = t >> 5, lane = t & 31;
    const unsigned full = 0xffffffffu;

    if (t < N_GT) {
        sg[t] = ((const float4*)gts)[t];
        slbl[t] = gt_labels[t];
    }
    __syncthreads();

    const int num_pos   = __ldcg(&g_npos);
    const int neg_total = __ldcg(&g_ntot);

    {
        int slot = bid * 4 + warp;          // 128 blocks x 4 warps = 512 slots
        bool is_pos = slot < num_pos;
        int e;
        if (is_pos) e = __ldcg(&g_pos_list[slot]);
        else {
            int j = slot - num_pos;
            e = (j < neg_total) ? __ldcg(&g_neg_list[j])
                                : __ldcg(&g_non_list[j - neg_total]);
        }
        int idx = e & 0xFFFF;
        int g   = e >> 16;
        int lbl = is_pos ? slbl[g] : 0;

        const float* row = score + (size_t)idx * NCLS;
        float v0 = row[lane];
        float v1 = row[lane + 32];
        float v2 = (lane + 64 < NCLS) ? row[lane + 64] : -INFINITY;
        float m = fmaxf(fmaxf(v0, v1), v2);
#pragma unroll
        for (int o = 16; o; o >>= 1) m = fmaxf(m, __shfl_xor_sync(full, m, o));
        float s = expf(v0 - m) + expf(v1 - m) + ((lane + 64 < NCLS) ? expf(v2 - m) : 0.0f);
#pragma unroll
        for (int o = 16; o; o >>= 1) s += __shfl_xor_sync(full, s, o);

        float cand = (lbl < 32) ? v0 : ((lbl < 64) ? v1 : v2);
        float vl = __shfl_sync(full, cand, lbl & 31);

        if (lane == 0) {
            float ce = m + logf(s) - vl;
            float rg = 0.0f;
            if (is_pos) {
                float4 pp = ((const float4*)props)[idx];
                float4 gb = sg[g];
                float pw = pp.z - pp.x, ph = pp.w - pp.y;
                float pcx = pp.x + 0.5f * pw, pcy = pp.y + 0.5f * ph;
                float gw = gb.z - gb.x, gh = gb.w - gb.y;
                float gcx = gb.x + 0.5f * gw, gcy = gb.y + 0.5f * gh;
                float t0 = ((gcx - pcx) / pw) * 10.0f;
                float t1 = ((gcy - pcy) / ph) * 10.0f;
                float t2 = logf(gw / pw) * 5.0f;
                float t3 = logf(gh / ph) * 5.0f;
                float4 pv = *(const float4*)(txty + ((size_t)idx * NCLS + g) * 4);
                rg = sl1(pv.x - t0) + sl1(pv.y - t1) + sl1(pv.z - t2) + sl1(pv.w - t3);
            }
            g_ce[slot] = ce;
            g_rg[slot] = rg;
        }
    }

    // last-arriving block reduces and resets replay state
    __syncthreads();
    if (t == 0) {
        __threadfence();
        s_last = (atomicAdd(&g_done, 1) == K3_NBLK - 1) ? 1 : 0;
    }
    __syncthreads();
    if (s_last) {
        __threadfence();
        float c  = __ldcg(&g_ce[t])       + __ldcg(&g_ce[t + 128])
                 + __ldcg(&g_ce[t + 256]) + __ldcg(&g_ce[t + 384]);
        float r2 = __ldcg(&g_rg[t])       + __ldcg(&g_rg[t + 128])
                 + __ldcg(&g_rg[t + 256]) + __ldcg(&g_rg[t + 384]);
#pragma unroll
        for (int o = 16; o; o >>= 1) {
            c  += __shfl_xor_sync(full, c, o);
            r2 += __shfl_xor_sync(full, r2, o);
        }
        if (lane == 0) { rc[warp] = c; rr[warp] = r2; }
        __syncthreads();
        if (warp == 0 && lane == 0) {
            float cc  = rc[0] + rc[1] + rc[2] + rc[3];
            float rrv = rr[0] + rr[1] + rr[2] + rr[3];
            out[0] = cc  * (1.0f / (float)TOTAL);
            out[1] = rrv * (1.0f / (float)TOTAL);
        }
        // reset for next graph replay (all other blocks already arrived)
        g_grp_pos[t]       = 0;
        g_grp_pos[t + 128] = 0;
        g_grp_neg[t]       = 0;
        g_grp_neg[t + 128] = 0;
        if (t == 0) g_done = 0;
    }
}

extern "C" void kernel_launch(void* const* d_in, const int* in_sizes, int n_in,
                              void* d_out, int out_size) {
    const float* props = (const float*)d_in[1];
    const float* score = (const float*)d_in[2];
    const float* txty  = (const float*)d_in[3];
    const float* gts   = (const float*)d_in[4];
    const int*   glbl  = (const int*)d_in[5];
    float* out = (float*)d_out;

    k_iou <<<K1_NBLK, K1_TPB>>>(props, gts);
    k_sel <<<NGRP,    K2_TPB>>>();
    k_loss<<<K3_NBLK, K3_TPB>>>(props, gts, glbl, score, txty, out);
}

// round 11
// speedup vs baseline: 1.6654x; 1.6654x over previous
#include <cuda_runtime.h>
#include <cuda_bf16.h>
#include <math.h>

#define N_PROP   65536
#define N_GT     64
#define NCLS     81
#define TOTAL    512
#define MAX_POS  128
#define TPB      1024
#define NBLK     128            // <= 148 SMs -> one block per SM, balanced
#define PPB      512            // proposals per block (2 threads each)
#define CHUNK    256
#define NCHUNK   256

// -------- device scratch --------
__device__ int   g_blk_pos[NCHUNK];
__device__ int   g_blk_neg[NCHUNK];
__device__ int   g_pos_list[TOTAL];   // packed (gt<<16)|i
__device__ int   g_neg_list[TOTAL];
__device__ int   g_non_list[TOTAL];
__device__ float g_ce[TOTAL];
__device__ float g_rg[TOTAL];
__device__ int          g_cntA[32];
__device__ volatile int g_genA[32];
__device__ int          g_cntB[32];
__device__ volatile int g_genB[32];
__device__ int          g_done;

__device__ __forceinline__ float sl1(float d) {
    float ad = fabsf(d);
    return (ad < 1.0f) ? (0.5f * d * d) : (ad - 0.5f);
}

__global__ void __launch_bounds__(TPB, 1)
k_fused(const float* __restrict__ props,
        const float* __restrict__ gts,
        const int*   __restrict__ gt_labels,
        const float* __restrict__ score,
        const float* __restrict__ txty,
        float* __restrict__ out,
        int n_gt) {
    __shared__ float4 sg[N_GT];
    __shared__ float  sS[N_GT];       // ga + 1e-8 (comparison fold)
    __shared__ float  sga[N_GT];      // raw ga (exact final union)
    __shared__ int    slbl[N_GT];
    __shared__ float  s_ci[PPB], s_cu[PPB];
    __shared__ int    s_cj[PPB];
    __shared__ int    wpc[16], wnc[16];     // half-0 warps
    __shared__ int    swp[8], swn[8];
    __shared__ int    ssp[NCHUNK], ssn[NCHUNK];
    __shared__ int    s_numpos, s_negtot;
    __shared__ int    s_offp[2], s_offn[2]; // per owned chunk
    __shared__ int    s_last;
    __shared__ float  rc[16], rr[16];

    const int t    = threadIdx.x;
    const int bid  = blockIdx.x;
    const int warp = t >> 5, lane = t & 31;
    const int half = t >> 9;                 // 0: gts [0,32), 1: gts [32,64)
    const int lp   = t & (PPB - 1);          // local proposal id 0..511
    const unsigned full = 0xffffffffu;

    // ---- stage gt data ----
    if (t < N_GT) {
        float4 g = ((const float4*)gts)[t];
        float ga = (g.z - g.x) * (g.w - g.y);
        sg[t]  = g;
        sga[t] = ga;
        sS[t]  = ga + 1e-8f;
        slbl[t] = gt_labels[t];
    }
    __syncthreads();

    // ============ phase 1: IoU argmax, 2 indep chains x 16 gts ============
    const int i = bid * PPB + lp;
    const float4 p = ((const float4*)props)[i];
    const float pa = (p.z - p.x) * (p.w - p.y);

    const int j0 = half * 32;
    float biA, bSA, biB, bSB;
    int   bjA, bjB;
    {
        float4 g = sg[j0];
        float ix = fmaxf(fminf(p.z, g.z) - fmaxf(p.x, g.x), 0.f);
        float iy = fmaxf(fminf(p.w, g.w) - fmaxf(p.y, g.y), 0.f);
        biA = ix * iy; bSA = pa + sS[j0]; bjA = j0;
        g = sg[j0 + 16];
        ix = fmaxf(fminf(p.z, g.z) - fmaxf(p.x, g.x), 0.f);
        iy = fmaxf(fminf(p.w, g.w) - fmaxf(p.y, g.y), 0.f);
        biB = ix * iy; bSB = pa + sS[j0 + 16]; bjB = j0 + 16;
    }
#pragma unroll
    for (int j = 1; j < 16; j++) {
        int jA = j0 + j, jB = j0 + 16 + j;
        float4 gA = sg[jA], gB = sg[jB];
        float SA = pa + sS[jA], SB = pa + sS[jB];
        float ixA = fmaxf(fminf(p.z, gA.z) - fmaxf(p.x, gA.x), 0.f);
        float iyA = fmaxf(fminf(p.w, gA.w) - fmaxf(p.y, gA.y), 0.f);
        float ixB = fmaxf(fminf(p.z, gB.z) - fmaxf(p.x, gB.x), 0.f);
        float iyB = fmaxf(fminf(p.w, gB.w) - fmaxf(p.y, gB.y), 0.f);
        float inA = ixA * iyA, inB = ixB * iyB;
        // iou_new > iou_best <=> in*bS > bi*S (union -inter terms cancel exactly)
        if (inA * bSA > biA * SA) { biA = inA; bSA = SA; bjA = jA; }
        if (inB * bSB > biB * SB) { biB = inB; bSB = SB; bjB = jB; }
    }
    if (biB * bSA > biA * bSB) { biA = biB; bSA = bSB; bjA = bjB; }  // B strictly higher idx

    if (half == 1) { s_ci[lp] = biA; s_cu[lp] = bSA; s_cj[lp] = bjA; }
    __syncthreads();

    int f = 0, bj = bjA;
    unsigned bp = 0, bn = 0;
    if (half == 0) {
        float ui = s_ci[lp], uS = s_cu[lp];
        if (ui * bSA > biA * uS) { biA = ui; bSA = uS; bjA = s_cj[lp]; }  // upper strictly greater
        bj = bjA;
        // exact final iou in reference association order
        float u = ((pa + sga[bj]) - biA) + 1e-8f;
        float miou = biA / u;
        f = (miou >= 0.5f) ? 1 : ((miou >= 0.1f) ? 2 : 0);
        bp = __ballot_sync(full, f == 1);
        bn = __ballot_sync(full, f == 2);
        if (lane == 0) { wpc[warp] = __popc(bp); wnc[warp] = __popc(bn); }
    }
    __syncthreads();
    if (t < 2) {        // chunk counts: warps 0-7 -> chunk 2bid, 8-15 -> 2bid+1
        int cp = 0, cn = 0;
#pragma unroll
        for (int w = 0; w < 8; w++) { cp += wpc[t * 8 + w]; cn += wnc[t * 8 + w]; }
        g_blk_pos[2 * bid + t] = cp;
        g_blk_neg[2 * bid + t] = cn;
    }

    // ============ barrier A (128 balanced arrivals) ============
    __syncthreads();
    if (t == 0) {
        __threadfence();
        if (atomicAdd(&g_cntA[0], 1) == NBLK - 1) {
            __threadfence();
            g_genA[0] = 1;
        } else {
            while (g_genA[0] == 0) { }
            __threadfence();
        }
    }
    __syncthreads();

    // ============ phase 2: scan 256 chunk counts (warps 0-7) ============
    if (t < NCHUNK) {
        int ip  = __ldcg(&g_blk_pos[t]);
        int in_ = __ldcg(&g_blk_neg[t]);
#pragma unroll
        for (int o = 1; o < 32; o <<= 1) {
            int ap = __shfl_up_sync(full, ip, o);
            int an = __shfl_up_sync(full, in_, o);
            if (lane >= o) { ip += ap; in_ += an; }
        }
        if (lane == 31) { swp[warp] = ip; swn[warp] = in_; }
        __syncthreads();
        int basep = 0, basen = 0;
        for (int w = 0; w < warp; w++) { basep += swp[w]; basen += swn[w]; }
        ssp[t] = basep + ip;
        ssn[t] = basen + in_;
    } else {
        __syncthreads();
    }
    __syncthreads();
    if (t < 2) {
        int c = 2 * bid + t;
        s_offp[t] = (c > 0) ? ssp[c - 1] : 0;
        s_offn[t] = (c > 0) ? ssn[c - 1] : 0;
        if (t == 0) {
            s_numpos = min(ssp[NCHUNK - 1], MAX_POS);
            s_negtot = ssn[NCHUNK - 1];
        }
    }
    __syncthreads();

    // ============ phase 2b: stable select -> global lists ============
    if (half == 0) {
        const int cg = warp >> 3;            // owned chunk: 0 or 1
        const int c  = 2 * bid + cg;
        int pre_p = 0, pre_n = 0;
        for (int w = cg * 8; w < warp; w++) { pre_p += wpc[w]; pre_n += wnc[w]; }
        unsigned lm = (1u << lane) - 1u;
        int neg_before = pre_n + __popc(bn & lm);
        const int localc = lp & (CHUNK - 1); // index within chunk
        if (f == 1) {
            int r = s_offp[cg] + pre_p + __popc(bp & lm);
            if (r < TOTAL) g_pos_list[r] = i | (bj << 16);
        } else if (f == 2) {
            int r = s_offn[cg] + neg_before;
            if (r < TOTAL) g_neg_list[r] = i;
        }
        if (f != 2) {
            int r = (c * CHUNK - s_offn[cg]) + (localc - neg_before);
            if (r < TOTAL) g_non_list[r] = i;
        }
    }

    // ============ barrier B ============
    __syncthreads();
    if (t == 0) {
        __threadfence();
        if (atomicAdd(&g_cntB[0], 1) == NBLK - 1) {
            __threadfence();
            g_genB[0] = 1;
        } else {
            while (g_genB[0] == 0) { }
            __threadfence();
        }
    }
    __syncthreads();

    // ============ phase 3: loss (4 warps/block -> 512 slots) ============
    if (warp < 4) {
        int slot = bid * 4 + warp;
        int num_pos = s_numpos;
        int neg_total = s_negtot;
        bool is_pos = slot < num_pos;
        int e;
        if (is_pos) e = __ldcg(&g_pos_list[slot]);
        else {
            int j = slot - num_pos;
            e = (j < neg_total) ? __ldcg(&g_neg_list[j])
                                : __ldcg(&g_non_list[j - neg_total]);
        }
        int idx = e & 0xFFFF;
        int g   = e >> 16;
        int lbl = is_pos ? slbl[g] : 0;

        const float* row = score + (size_t)idx * NCLS;
        float v0 = row[lane];
        float v1 = row[lane + 32];
        float v2 = (lane + 64 < NCLS) ? row[lane + 64] : -INFINITY;
        float m = fmaxf(fmaxf(v0, v1), v2);
#pragma unroll
        for (int o = 16; o; o >>= 1) m = fmaxf(m, __shfl_xor_sync(full, m, o));
        float s = expf(v0 - m) + expf(v1 - m) + ((lane + 64 < NCLS) ? expf(v2 - m) : 0.0f);
#pragma unroll
        for (int o = 16; o; o >>= 1) s += __shfl_xor_sync(full, s, o);

        float cand = (lbl < 32) ? v0 : ((lbl < 64) ? v1 : v2);
        float vl = __shfl_sync(full, cand, lbl & 31);

        if (lane == 0) {
            float ce = m + logf(s) - vl;
            float rg = 0.0f;
            if (is_pos) {
                float4 pp = ((const float4*)props)[idx];
                float4 gb = sg[g];
                float pw = pp.z - pp.x, ph = pp.w - pp.y;
                float pcx = pp.x + 0.5f * pw, pcy = pp.y + 0.5f * ph;
                float gw = gb.z - gb.x, gh = gb.w - gb.y;
                float gcx = gb.x + 0.5f * gw, gcy = gb.y + 0.5f * gh;
                float t0 = ((gcx - pcx) / pw) * 10.0f;
                float t1 = ((gcy - pcy) / ph) * 10.0f;
                float t2 = logf(gw / pw) * 5.0f;
                float t3 = logf(gh / ph) * 5.0f;
                float4 pv = *(const float4*)(txty + ((size_t)idx * NCLS + g) * 4);
                rg = sl1(pv.x - t0) + sl1(pv.y - t1) + sl1(pv.z - t2) + sl1(pv.w - t3);
            }
            g_ce[slot] = ce;
            g_rg[slot] = rg;
        }
    }

    // ============ phase 4: last-arriving block reduces, resets state ========
    __syncthreads();
    if (t == 0) {
        __threadfence();
        s_last = (atomicAdd(&g_done, 1) == NBLK - 1) ? 1 : 0;
    }
    __syncthreads();
    if (s_last) {
        if (t < TOTAL) {
            __threadfence();
            float c  = __ldcg(&g_ce[t]);
            float r2 = __ldcg(&g_rg[t]);
#pragma unroll
            for (int o = 16; o; o >>= 1) {
                c  += __shfl_xor_sync(full, c, o);
                r2 += __shfl_xor_sync(full, r2, o);
            }
            if (lane == 0) { rc[warp] = c; rr[warp] = r2; }
        }
        __syncthreads();
        if (warp == 0) {
            float cc  = (lane < 16) ? rc[lane] : 0.0f;
            float rrv = (lane < 16) ? rr[lane] : 0.0f;
#pragma unroll
            for (int o = 8; o; o >>= 1) {
                cc  += __shfl_xor_sync(full, cc, o);
                rrv += __shfl_xor_sync(full, rrv, o);
            }
            if (lane == 0) {
                out[0] = cc  * (1.0f / (float)TOTAL);
                out[1] = rrv * (1.0f / (float)TOTAL);
            }
        }
        // reset barrier state for next graph replay
        if (t == 0) {
            g_cntA[0] = 0; g_genA[0] = 0;
            g_cntB[0] = 0; g_genB[0] = 0;
            g_done    = 0;
        }
    }
}

extern "C" void kernel_launch(void* const* d_in, const int* in_sizes, int n_in,
                              void* d_out, int out_size) {
    const float* props = (const float*)d_in[1];
    const float* score = (const float*)d_in[2];
    const float* txty  = (const float*)d_in[3];
    const float* gts   = (const float*)d_in[4];
    const int*   glbl  = (const int*)d_in[5];
    float* out = (float*)d_out;
    int n_gt = in_sizes[4] / 4;

    k_fused<<<NBLK, TPB>>>(props, gts, glbl, score, txty, out, n_gt);
}